// round 6
// baseline (speedup 1.0000x reference)
#include <cuda_runtime.h>
#include <cuda_bf16.h>
#include <cstdint>

// ---------------- problem constants ----------------
#define NN     50000
#define IN_C   128
#define HID    64
#define HEADS  4
#define OUT_C  64
#define EMAX   800000
#define ETOT   (EMAX + NN)     // with self loops

// ---------------- scratch (device globals; no allocation allowed) ----------
__device__ float g_h [ (size_t)NN * (HEADS*HID) ]; // GEMM output / features h
__device__ float g_x [ (size_t)NN * (HEADS*HID) ]; // layer output / next GEMM input
__device__ float g_as[ NN * HEADS ];
__device__ float g_ad[ NN * HEADS ];
__device__ int   g_off[ NN + 1 ];
__device__ int   g_cnt[ NN ];
__device__ int   g_cur[ NN ];
__device__ int   g_srt[ ETOT ];
__device__ float g_sum[ HID ];
__device__ int   g_is64;          // edge_index dtype flag (auto-detected)

// ---------------- edge_index dtype detection ----------------
// If the buffer holds int64 node ids (< 2^31), every odd int32 word (hi word,
// little-endian) is zero. For int32 random ids in [0,50000), 64 consecutive
// odd words all-zero is impossible in practice.
__global__ void detect_kernel(const int* __restrict__ ei32) {
    if (threadIdx.x == 0 && blockIdx.x == 0) {
        int odd_or = 0;
#pragma unroll
        for (int i = 0; i < 64; i++) odd_or |= ei32[2 * i + 1];
        g_is64 = (odd_or == 0) ? 1 : 0;
    }
}

__device__ __forceinline__ int edge_src(const int* ei32, int E, int i) {
    return g_is64 ? ei32[2 * i] : ei32[i];
}
__device__ __forceinline__ int edge_dst(const int* ei32, int E, int i) {
    return g_is64 ? ei32[2 * (E + i)] : ei32[E + i];
}

// ---------------- CSR build ----------------
__global__ void init_cnt_kernel(int n) {
    int i = blockIdx.x * blockDim.x + threadIdx.x;
    if (i < n) g_cnt[i] = 1;   // self loop
}

__global__ void hist_kernel(const int* __restrict__ ei, int E) {
    int i = blockIdx.x * blockDim.x + threadIdx.x;
    if (i < E) atomicAdd(&g_cnt[edge_dst(ei, E, i)], 1);
}

__global__ void scan_kernel(int n) {
    __shared__ int sh[1024];
    int t = threadIdx.x;
    int chunk = (n + 1023) / 1024;
    int start = t * chunk;
    int end = start + chunk; if (end > n) end = n;
    int s = 0;
    for (int i = start; i < end; i++) s += g_cnt[i];
    sh[t] = s;
    __syncthreads();
    // Hillis-Steele inclusive scan
    for (int d = 1; d < 1024; d <<= 1) {
        int v = (t >= d) ? sh[t - d] : 0;
        __syncthreads();
        sh[t] += v;
        __syncthreads();
    }
    int run = (t == 0) ? 0 : sh[t - 1];
    for (int i = start; i < end; i++) {
        g_off[i] = run;
        g_cur[i] = run;
        run += g_cnt[i];
    }
    if (t == 1023) g_off[n] = sh[1023];
}

__global__ void scatter_kernel(const int* __restrict__ ei, int E, int n) {
    int i = blockIdx.x * blockDim.x + threadIdx.x;
    int total = E + n;
    if (i >= total) return;
    int s, d;
    if (i < E) { s = edge_src(ei, E, i); d = edge_dst(ei, E, i); }
    else       { s = d = i - E; }
    int pos = atomicAdd(&g_cur[d], 1);
    g_srt[pos] = s;
}

// ---------------- SGEMM: g_h[N,M] = A[N,K] @ B[K,M] ----------------
// A = external input (FROM_GLOBAL=false) or g_x (FROM_GLOBAL=true).
// BM=128 BN=64 BK=16, 256 threads, 8x4 microtile. K % 16 == 0, M % 64 == 0.
template<bool FROM_GLOBAL>
__global__ __launch_bounds__(256) void sgemm_kernel(
    const float* __restrict__ Ain, const float* __restrict__ B,
    int Nrows, int K, int M)
{
    const float* A = FROM_GLOBAL ? g_x : Ain;
    float* C = g_h;
    __shared__ float As[16][128];
    __shared__ float Bs[16][64];
    int tid  = threadIdx.x;
    int row0 = blockIdx.y * 128;
    int col0 = blockIdx.x * 64;
    int tx = tid & 15;       // col group 0..15 (4 cols each)
    int ty = tid >> 4;       // row group 0..15 (8 rows each)

    float acc[8][4];
#pragma unroll
    for (int i = 0; i < 8; i++)
#pragma unroll
        for (int j = 0; j < 4; j++) acc[i][j] = 0.f;

    for (int k0 = 0; k0 < K; k0 += 16) {
        // load A tile 128x16 (512 float4)
#pragma unroll
        for (int s = 0; s < 2; s++) {
            int idx = tid + s * 256;
            int r   = idx >> 2;
            int c4  = idx & 3;
            int grow = row0 + r;
            float4 v = make_float4(0.f, 0.f, 0.f, 0.f);
            if (grow < Nrows)
                v = *reinterpret_cast<const float4*>(A + (size_t)grow * K + k0 + c4 * 4);
            As[c4 * 4 + 0][r] = v.x;
            As[c4 * 4 + 1][r] = v.y;
            As[c4 * 4 + 2][r] = v.z;
            As[c4 * 4 + 3][r] = v.w;
        }
        // load B tile 16x64 (256 float4)
        {
            int r  = tid >> 4;    // k 0..15
            int c4 = tid & 15;    // 0..15
            float4 v = *reinterpret_cast<const float4*>(B + (size_t)(k0 + r) * M + col0 + c4 * 4);
            *reinterpret_cast<float4*>(&Bs[r][c4 * 4]) = v;
        }
        __syncthreads();
#pragma unroll
        for (int k = 0; k < 16; k++) {
            float a[8], b[4];
            float4 a0 = *reinterpret_cast<const float4*>(&As[k][ty * 8]);
            float4 a1 = *reinterpret_cast<const float4*>(&As[k][ty * 8 + 4]);
            a[0]=a0.x; a[1]=a0.y; a[2]=a0.z; a[3]=a0.w;
            a[4]=a1.x; a[5]=a1.y; a[6]=a1.z; a[7]=a1.w;
            float4 b0 = *reinterpret_cast<const float4*>(&Bs[k][tx * 4]);
            b[0]=b0.x; b[1]=b0.y; b[2]=b0.z; b[3]=b0.w;
#pragma unroll
            for (int i = 0; i < 8; i++)
#pragma unroll
                for (int j = 0; j < 4; j++)
                    acc[i][j] += a[i] * b[j];
        }
        __syncthreads();
    }
#pragma unroll
    for (int i = 0; i < 8; i++) {
        int grow = row0 + ty * 8 + i;
        if (grow < Nrows) {
            float4 v = make_float4(acc[i][0], acc[i][1], acc[i][2], acc[i][3]);
            *reinterpret_cast<float4*>(C + (size_t)grow * M + col0 + tx * 4) = v;
        }
    }
}

// ---------------- attention coefficients: alpha_s/alpha_d per node ----------
// reads g_h, writes g_as/g_ad
template<int H>
__global__ void alpha_kernel(const float* __restrict__ a_s,
                             const float* __restrict__ a_d, int n)
{
    int w = (blockIdx.x * blockDim.x + threadIdx.x) >> 5;
    int lane = threadIdx.x & 31;
    if (w >= n) return;
    constexpr int FPL = 2 * H;
    float ps[H], pd[H];
#pragma unroll
    for (int hh = 0; hh < H; hh++) { ps[hh] = 0.f; pd[hh] = 0.f; }
    const float* row = g_h + (size_t)w * (H * 64);
#pragma unroll
    for (int j = 0; j < FPL; j++) {
        float v = row[lane + 32 * j];
        int hh = j >> 1;
        int c  = lane + 32 * (j & 1);
        ps[hh] += v * a_s[hh * 64 + c];
        pd[hh] += v * a_d[hh * 64 + c];
    }
#pragma unroll
    for (int hh = 0; hh < H; hh++) {
        float s = ps[hh], d = pd[hh];
#pragma unroll
        for (int o = 16; o; o >>= 1) {
            s += __shfl_xor_sync(0xffffffffu, s, o);
            d += __shfl_xor_sync(0xffffffffu, d, o);
        }
        if (lane == 0) { g_as[w * H + hh] = s; g_ad[w * H + hh] = d; }
    }
}

// ---------------- fused edge softmax + aggregation (one warp per dst) -------
// reads g_h/g_as/g_ad/g_off/g_srt, writes g_x
template<int FPL, int H, bool RELU>
__global__ __launch_bounds__(256) void agg_kernel(
    const float* __restrict__ bias, int n)
{
    int w = (blockIdx.x * blockDim.x + threadIdx.x) >> 5;
    int lane = threadIdx.x & 31;
    if (w >= n) return;
    constexpr int FEAT = FPL * 32;

    float adv[H];
#pragma unroll
    for (int hh = 0; hh < H; hh++) adv[hh] = g_ad[w * H + hh];

    float m[H], den[H], acc[FPL];
#pragma unroll
    for (int hh = 0; hh < H; hh++) { m[hh] = -1e30f; den[hh] = 0.f; }
#pragma unroll
    for (int j = 0; j < FPL; j++) acc[j] = 0.f;

    int e1 = g_off[w + 1];
    for (int e = g_off[w]; e < e1; e++) {
        int s = g_srt[e];                       // same for all lanes -> broadcast
        const float* hr = g_h + (size_t)s * FEAT;
        float v[FPL];
#pragma unroll
        for (int j = 0; j < FPL; j++) v[j] = hr[lane + 32 * j];

        float asv[H];
        if constexpr (H == 4) {
            float4 t = *reinterpret_cast<const float4*>(g_as + (size_t)s * 4);
            asv[0] = t.x; asv[1] = t.y; asv[2] = t.z; asv[3] = t.w;
        } else {
            asv[0] = g_as[s];
        }
#pragma unroll
        for (int hh = 0; hh < H; hh++) {
            float eh = asv[hh] + adv[hh];
            eh = (eh > 0.f) ? eh : 0.2f * eh;     // leaky_relu(0.2)
            float wgt;
            if (eh > m[hh]) {
                float sc = __expf(m[hh] - eh);    // exp(-inf)=0 on first edge
                den[hh] = den[hh] * sc + 1.f;
                acc[2 * hh]     *= sc;
                acc[2 * hh + 1] *= sc;
                m[hh] = eh;
                wgt = 1.f;
            } else {
                wgt = __expf(eh - m[hh]);
                den[hh] += wgt;
            }
            acc[2 * hh]     += wgt * v[2 * hh];
            acc[2 * hh + 1] += wgt * v[2 * hh + 1];
        }
    }
#pragma unroll
    for (int j = 0; j < FPL; j++) {
        int col = lane + 32 * j;
        float o = acc[j] / den[j >> 1] + bias[col];
        if (RELU) o = fmaxf(o, 0.f);
        g_x[(size_t)w * FEAT + col] = o;
    }
}

// ---------------- mean over nodes + linear head ----------------
__global__ void zero_sum_kernel() {
    g_sum[threadIdx.x] = 0.f;
}

__global__ void colsum_kernel(int n) {
    int col = threadIdx.x;                 // 64 threads
    int r0 = blockIdx.x * 256;
    int r1 = r0 + 256; if (r1 > n) r1 = n;
    float s = 0.f;
    for (int r = r0; r < r1; r++) s += g_x[(size_t)r * 64 + col];
    atomicAdd(&g_sum[col], s);
}

__global__ void head_kernel(const float* __restrict__ hw,
                            const float* __restrict__ hb,
                            float* __restrict__ out, int n) {
    __shared__ float g[64];
    int t = threadIdx.x;
    g[t] = g_sum[t] / (float)n;
    __syncthreads();
    float o = hb[t];
#pragma unroll
    for (int c = 0; c < 64; c++) o += g[c] * hw[c * 64 + t];
    out[t] = o;
}

// ---------------- launch (kernel launches ONLY; graph-capturable) ----------
extern "C" void kernel_launch(void* const* d_in, const int* in_sizes, int n_in,
                              void* d_out, int out_size) {
    const float* x   = (const float*)d_in[0];
    const int*   ei  = (const int*)d_in[1];     // int32 OR int64 (auto-detected)
    const float* W0  = (const float*)d_in[2];
    const float* a0s = (const float*)d_in[3];
    const float* a0d = (const float*)d_in[4];
    const float* b0  = (const float*)d_in[5];
    const float* W1  = (const float*)d_in[6];
    const float* a1s = (const float*)d_in[7];
    const float* a1d = (const float*)d_in[8];
    const float* b1  = (const float*)d_in[9];
    const float* W2  = (const float*)d_in[10];
    const float* a2s = (const float*)d_in[11];
    const float* a2d = (const float*)d_in[12];
    const float* b2  = (const float*)d_in[13];
    const float* hw  = (const float*)d_in[14];
    const float* hb  = (const float*)d_in[15];
    float* out = (float*)d_out;

    const int N = in_sizes[0] / IN_C;
    const int E = in_sizes[1] / 2;   // element count is dtype-independent

    // ---- CSR by dst (recomputed each launch; deterministic work) ----
    detect_kernel<<<1, 32>>>(ei);
    init_cnt_kernel<<<(N + 255) / 256, 256>>>(N);
    hist_kernel<<<(E + 255) / 256, 256>>>(ei, E);
    scan_kernel<<<1, 1024>>>(N);
    scatter_kernel<<<((E + N) + 255) / 256, 256>>>(ei, E, N);

    const int warpBlocks = (N * 32 + 255) / 256;

    // ---- layer 0: 128 -> 4x64 ----
    {
        dim3 g(256 / 64, (N + 127) / 128);
        sgemm_kernel<false><<<g, 256>>>(x, W0, N, 128, 256);
    }
    alpha_kernel<4><<<warpBlocks, 256>>>(a0s, a0d, N);
    agg_kernel<8, 4, true><<<warpBlocks, 256>>>(b0, N);

    // ---- layer 1: 256 -> 4x64 ----
    {
        dim3 g(256 / 64, (N + 127) / 128);
        sgemm_kernel<true><<<g, 256>>>(nullptr, W1, N, 256, 256);
    }
    alpha_kernel<4><<<warpBlocks, 256>>>(a1s, a1d, N);
    agg_kernel<8, 4, true><<<warpBlocks, 256>>>(b1, N);

    // ---- layer 2: 256 -> 1x64 (no relu) ----
    {
        dim3 g(64 / 64, (N + 127) / 128);
        sgemm_kernel<true><<<g, 256>>>(nullptr, W2, N, 256, 64);
    }
    alpha_kernel<1><<<warpBlocks, 256>>>(a2s, a2d, N);
    agg_kernel<2, 1, false><<<warpBlocks, 256>>>(b2, N);

    // ---- mean over nodes + linear head ----
    zero_sum_kernel<<<1, 64>>>();
    colsum_kernel<<<(N + 255) / 256, 64>>>(N);
    head_kernel<<<1, 64>>>(hw, hb, out, N);
}